// round 3
// baseline (speedup 1.0000x reference)
#include <cuda_runtime.h>

#define NNODES 100000
#define NF4    (NNODES * 16)
#define EMAX   1600000

typedef unsigned long long ull;

// ---------------- scratch (device globals; no allocs allowed) ----------------
__device__ float4 g_y[NF4];               // l-path transformed features
__device__ float4 g_r[NF4];               // root-path features
__device__ float4 g_h[NF4];               // hidden activations
__device__ int    g_cnt[NNODES];
__device__ int    g_rowptr[NNODES + 1];
__device__ int    g_cursor[NNODES];
__device__ int    g_eidx[EMAX];
__device__ ulonglong2 g_w1l[83 * 64], g_w1r[83 * 64];   // dup-packed weights, KP=166
__device__ ulonglong2 g_w2l[32 * 64], g_w2r[32 * 64];   // KP=64

// ---------------- packed f32x2 helpers ----------------
static __device__ __forceinline__ ull pk2(float a, float b) {
    ull r; asm("mov.b64 %0, {%1, %2};" : "=l"(r) : "f"(a), "f"(b)); return r;
}
static __device__ __forceinline__ void ffma2(ull& d, ull a, ull b) {
    asm("fma.rn.f32x2 %0, %1, %2, %0;" : "+l"(d) : "l"(a), "l"(b));
}
static __device__ __forceinline__ float2 upk(ull v) {
    float2 r; asm("mov.b64 {%0, %1}, %2;" : "=f"(r.x), "=f"(r.y) : "l"(v)); return r;
}

// ---------------- weight dup-pack: wp[g*64+col] = (dup w[2g][col], dup w[2g+1][col]) ----
__global__ void pack_w(const float* __restrict__ w, ulonglong2* __restrict__ wp,
                       int K, int G) {
    int i = blockIdx.x * blockDim.x + threadIdx.x;
    if (i >= G * 64) return;
    int g = i >> 6, col = i & 63;
    int k0 = 2 * g, k1 = 2 * g + 1;
    float w0 = (k0 < K) ? w[k0 * 64 + col] : 0.f;
    float w1 = (k1 < K) ? w[k1 * 64 + col] : 0.f;
    wp[i] = make_ulonglong2(pk2(w0, w0), pk2(w1, w1));
}

// ---------------- CSR build ----------------
__global__ void zero_cnt_k(int* __restrict__ c, int n) {
    int i = blockIdx.x * blockDim.x + threadIdx.x;
    if (i < n) c[i] = 0;
}
__global__ void hist_k(const int* __restrict__ dst, int* __restrict__ cnt, int E) {
    int e = blockIdx.x * blockDim.x + threadIdx.x;
    if (e < E) atomicAdd(&cnt[dst[e]], 1);
}
// single-block exclusive scan of cnt -> rowptr, cursor
__global__ __launch_bounds__(1024) void scan_k(const int* __restrict__ cnt,
                                               int* __restrict__ rowptr,
                                               int* __restrict__ cursor, int N) {
    __shared__ int ssum[1024];
    int t = threadIdx.x;
    int CH = (N + 1023) / 1024;
    int lo = t * CH, hi = min(lo + CH, N);
    int s = 0;
    for (int i = lo; i < hi; i++) s += cnt[i];
    ssum[t] = s;
    __syncthreads();
    for (int off = 1; off < 1024; off <<= 1) {
        int v = 0;
        if (t >= off) v = ssum[t - off];
        __syncthreads();
        if (t >= off) ssum[t] += v;
        __syncthreads();
    }
    int pre = (t == 0) ? 0 : ssum[t - 1];
    for (int i = lo; i < hi; i++) {
        rowptr[i] = pre; cursor[i] = pre;
        pre += cnt[i];
    }
    if (t == 1023) rowptr[N] = ssum[1023];
}
__global__ void fill_k(const int* __restrict__ src, const int* __restrict__ dst,
                       int* __restrict__ cursor, int* __restrict__ eidx, int E) {
    int e = blockIdx.x * blockDim.x + threadIdx.x;
    if (e >= E) return;
    int slot = atomicAdd(&cursor[dst[e]], 1);
    eidx[slot] = src[e];
}

// ---------------- dual GEMM: Yl = X@Wl, Yr = X@Wr  (X:[nrows,K], W packed) ----------
// 64 rows x 64 cols per block, 256 threads. Thread: 8 rows (4 f32x2 pairs) x 2 cols.
template <int K, int KP>
__global__ __launch_bounds__(256) void gemm_dual(
    const float* __restrict__ X,
    const ulonglong2* __restrict__ WlP, const ulonglong2* __restrict__ WrP,
    float* __restrict__ Yl, float* __restrict__ Yr, int nrows) {
    __shared__ float xsT[KP * 68];
    int n0 = blockIdx.x * 64;
    for (int i = threadIdx.x; i < 64 * KP; i += 256) {
        int rr = i / KP, k = i - rr * KP;
        float v = 0.f;
        if (k < K && n0 + rr < nrows) v = X[(size_t)(n0 + rr) * K + k];
        xsT[k * 68 + rr] = v;
    }
    __syncthreads();

    int c0 = threadIdx.x & 31, c1 = c0 + 32;
    int rb = (threadIdx.x >> 5) * 8;
    ull al0[4] = {}, al1[4] = {}, ar0[4] = {}, ar1[4] = {};

#pragma unroll 4
    for (int g = 0; g < KP / 2; g++) {
        int k = 2 * g;
        ulonglong2 a0 = *reinterpret_cast<const ulonglong2*>(&xsT[k * 68 + rb]);
        ulonglong2 a1 = *reinterpret_cast<const ulonglong2*>(&xsT[k * 68 + rb + 4]);
        ulonglong2 b0 = *reinterpret_cast<const ulonglong2*>(&xsT[(k + 1) * 68 + rb]);
        ulonglong2 b1 = *reinterpret_cast<const ulonglong2*>(&xsT[(k + 1) * 68 + rb + 4]);
        ulonglong2 wl0 = WlP[g * 64 + c0], wl1 = WlP[g * 64 + c1];
        ulonglong2 wr0 = WrP[g * 64 + c0], wr1 = WrP[g * 64 + c1];
        // k
        ffma2(al0[0], a0.x, wl0.x); ffma2(al0[1], a0.y, wl0.x);
        ffma2(al0[2], a1.x, wl0.x); ffma2(al0[3], a1.y, wl0.x);
        ffma2(al1[0], a0.x, wl1.x); ffma2(al1[1], a0.y, wl1.x);
        ffma2(al1[2], a1.x, wl1.x); ffma2(al1[3], a1.y, wl1.x);
        ffma2(ar0[0], a0.x, wr0.x); ffma2(ar0[1], a0.y, wr0.x);
        ffma2(ar0[2], a1.x, wr0.x); ffma2(ar0[3], a1.y, wr0.x);
        ffma2(ar1[0], a0.x, wr1.x); ffma2(ar1[1], a0.y, wr1.x);
        ffma2(ar1[2], a1.x, wr1.x); ffma2(ar1[3], a1.y, wr1.x);
        // k+1
        ffma2(al0[0], b0.x, wl0.y); ffma2(al0[1], b0.y, wl0.y);
        ffma2(al0[2], b1.x, wl0.y); ffma2(al0[3], b1.y, wl0.y);
        ffma2(al1[0], b0.x, wl1.y); ffma2(al1[1], b0.y, wl1.y);
        ffma2(al1[2], b1.x, wl1.y); ffma2(al1[3], b1.y, wl1.y);
        ffma2(ar0[0], b0.x, wr0.y); ffma2(ar0[1], b0.y, wr0.y);
        ffma2(ar0[2], b1.x, wr0.y); ffma2(ar0[3], b1.y, wr0.y);
        ffma2(ar1[0], b0.x, wr1.y); ffma2(ar1[1], b0.y, wr1.y);
        ffma2(ar1[2], b1.x, wr1.y); ffma2(ar1[3], b1.y, wr1.y);
    }

#pragma unroll
    for (int p = 0; p < 4; p++) {
        int row = n0 + rb + 2 * p;
        float2 l0 = upk(al0[p]), l1 = upk(al1[p]);
        float2 r0 = upk(ar0[p]), r1 = upk(ar1[p]);
        if (row < nrows) {
            Yl[(size_t)row * 64 + c0] = l0.x; Yl[(size_t)row * 64 + c1] = l1.x;
            Yr[(size_t)row * 64 + c0] = r0.x; Yr[(size_t)row * 64 + c1] = r1.x;
        }
        if (row + 1 < nrows) {
            Yl[(size_t)(row + 1) * 64 + c0] = l0.y; Yl[(size_t)(row + 1) * 64 + c1] = l1.y;
            Yr[(size_t)(row + 1) * 64 + c0] = r0.y; Yr[(size_t)(row + 1) * 64 + c1] = r1.y;
        }
    }
}

// ---------------- layer-1 aggregate + finalize: h = relu(mean + b + r) ----------------
__global__ void agg1_k(const int* __restrict__ rowptr, const int* __restrict__ eidx,
                       const float4* __restrict__ y, const float4* __restrict__ r,
                       const float* __restrict__ b, float4* __restrict__ h, int N) {
    int t = blockIdx.x * blockDim.x + threadIdx.x;
    int node = t >> 4, c = t & 15;
    if (node >= N) return;
    int beg = rowptr[node], end = rowptr[node + 1];
    float4 acc = make_float4(0.f, 0.f, 0.f, 0.f);
    float4 acc2 = make_float4(0.f, 0.f, 0.f, 0.f);
    int j = beg;
    for (; j + 2 <= end; j += 2) {
        int s0 = __ldg(&eidx[j]), s1 = __ldg(&eidx[j + 1]);
        float4 v0 = y[(size_t)s0 * 16 + c];
        float4 v1 = y[(size_t)s1 * 16 + c];
        acc.x += v0.x; acc.y += v0.y; acc.z += v0.z; acc.w += v0.w;
        acc2.x += v1.x; acc2.y += v1.y; acc2.z += v1.z; acc2.w += v1.w;
    }
    if (j < end) {
        int s0 = __ldg(&eidx[j]);
        float4 v0 = y[(size_t)s0 * 16 + c];
        acc.x += v0.x; acc.y += v0.y; acc.z += v0.z; acc.w += v0.w;
    }
    acc.x += acc2.x; acc.y += acc2.y; acc.z += acc2.z; acc.w += acc2.w;
    float inv = 1.f / fmaxf((float)(end - beg), 1.f);
    float4 rr = r[(size_t)node * 16 + c];
    float4 bb = reinterpret_cast<const float4*>(b)[c];
    float4 o;
    o.x = fmaxf(fmaf(acc.x, inv, bb.x + rr.x), 0.f);
    o.y = fmaxf(fmaf(acc.y, inv, bb.y + rr.y), 0.f);
    o.z = fmaxf(fmaf(acc.z, inv, bb.z + rr.z), 0.f);
    o.w = fmaxf(fmaf(acc.w, inv, bb.w + rr.w), 0.f);
    h[(size_t)node * 16 + c] = o;
}

// ------- layer-2 aggregate + finalize + classifier: out = relu(mean+b+r) @ Wc + bc ----
__global__ void agg2_k(const int* __restrict__ rowptr, const int* __restrict__ eidx,
                       const float4* __restrict__ y, const float4* __restrict__ r,
                       const float* __restrict__ b, const float* __restrict__ Wc,
                       const float* __restrict__ bc, float* __restrict__ out, int N) {
    int t = blockIdx.x * blockDim.x + threadIdx.x;
    int node = t >> 4, c = t & 15;
    if (node >= N) return;
    int beg = rowptr[node], end = rowptr[node + 1];
    float4 acc = make_float4(0.f, 0.f, 0.f, 0.f);
    float4 acc2 = make_float4(0.f, 0.f, 0.f, 0.f);
    int j = beg;
    for (; j + 2 <= end; j += 2) {
        int s0 = __ldg(&eidx[j]), s1 = __ldg(&eidx[j + 1]);
        float4 v0 = y[(size_t)s0 * 16 + c];
        float4 v1 = y[(size_t)s1 * 16 + c];
        acc.x += v0.x; acc.y += v0.y; acc.z += v0.z; acc.w += v0.w;
        acc2.x += v1.x; acc2.y += v1.y; acc2.z += v1.z; acc2.w += v1.w;
    }
    if (j < end) {
        int s0 = __ldg(&eidx[j]);
        float4 v0 = y[(size_t)s0 * 16 + c];
        acc.x += v0.x; acc.y += v0.y; acc.z += v0.z; acc.w += v0.w;
    }
    acc.x += acc2.x; acc.y += acc2.y; acc.z += acc2.z; acc.w += acc2.w;
    float inv = 1.f / fmaxf((float)(end - beg), 1.f);
    float4 rr = r[(size_t)node * 16 + c];
    float4 bb = reinterpret_cast<const float4*>(b)[c];
    float4 hv;
    hv.x = fmaxf(fmaf(acc.x, inv, bb.x + rr.x), 0.f);
    hv.y = fmaxf(fmaf(acc.y, inv, bb.y + rr.y), 0.f);
    hv.z = fmaxf(fmaf(acc.z, inv, bb.z + rr.z), 0.f);
    hv.w = fmaxf(fmaf(acc.w, inv, bb.w + rr.w), 0.f);
    // classifier partials: rows 4c..4c+3 of Wc[64,2]
    float4 wc0 = reinterpret_cast<const float4*>(Wc)[2 * c];
    float4 wc1 = reinterpret_cast<const float4*>(Wc)[2 * c + 1];
    float a0 = hv.x * wc0.x + hv.y * wc0.z + hv.z * wc1.x + hv.w * wc1.z;
    float a1 = hv.x * wc0.y + hv.y * wc0.w + hv.z * wc1.y + hv.w * wc1.w;
#pragma unroll
    for (int o = 8; o; o >>= 1) {
        a0 += __shfl_xor_sync(0xffffffffu, a0, o);
        a1 += __shfl_xor_sync(0xffffffffu, a1, o);
    }
    if (c == 0) {
        out[node * 2]     = a0 + bc[0];
        out[node * 2 + 1] = a1 + bc[1];
    }
}

extern "C" void kernel_launch(void* const* d_in, const int* in_sizes, int n_in,
                              void* d_out, int out_size) {
    const float* x   = (const float*)d_in[0];
    const int*   ei  = (const int*)d_in[1];
    const float* W1l = (const float*)d_in[2];
    const float* b1  = (const float*)d_in[3];
    const float* W1r = (const float*)d_in[4];
    const float* W2l = (const float*)d_in[5];
    const float* b2  = (const float*)d_in[6];
    const float* W2r = (const float*)d_in[7];
    const float* Wc  = (const float*)d_in[8];
    const float* bc  = (const float*)d_in[9];
    float* out = (float*)d_out;

    const int N = in_sizes[0] / 165;
    const int E = in_sizes[1] / 2;
    const int* src = ei;
    const int* dst = ei + E;

    float4 *yp, *rp, *hp;
    int *cntp, *rowp, *curp, *eixp;
    ulonglong2 *w1lp, *w1rp, *w2lp, *w2rp;
    cudaGetSymbolAddress((void**)&yp,   g_y);
    cudaGetSymbolAddress((void**)&rp,   g_r);
    cudaGetSymbolAddress((void**)&hp,   g_h);
    cudaGetSymbolAddress((void**)&cntp, g_cnt);
    cudaGetSymbolAddress((void**)&rowp, g_rowptr);
    cudaGetSymbolAddress((void**)&curp, g_cursor);
    cudaGetSymbolAddress((void**)&eixp, g_eidx);
    cudaGetSymbolAddress((void**)&w1lp, g_w1l);
    cudaGetSymbolAddress((void**)&w1rp, g_w1r);
    cudaGetSymbolAddress((void**)&w2lp, g_w2l);
    cudaGetSymbolAddress((void**)&w2rp, g_w2r);

    const int TB = 256;

    // weight packing (cheap, once per launch)
    pack_w<<<(83 * 64 + TB - 1) / TB, TB>>>(W1l, w1lp, 165, 83);
    pack_w<<<(83 * 64 + TB - 1) / TB, TB>>>(W1r, w1rp, 165, 83);
    pack_w<<<(32 * 64 + TB - 1) / TB, TB>>>(W2l, w2lp, 64, 32);
    pack_w<<<(32 * 64 + TB - 1) / TB, TB>>>(W2r, w2rp, 64, 32);

    // CSR build (shared by both layers)
    zero_cnt_k<<<(N + TB - 1) / TB, TB>>>(cntp, N);
    hist_k<<<(E + TB - 1) / TB, TB>>>(dst, cntp, E);
    scan_k<<<1, 1024>>>(cntp, rowp, curp, N);
    fill_k<<<(E + TB - 1) / TB, TB>>>(src, dst, curp, eixp, E);

    // ---- layer 1 ----
    gemm_dual<165, 166><<<(N + 63) / 64, TB>>>(x, w1lp, w1rp, (float*)yp, (float*)rp, N);
    agg1_k<<<((size_t)N * 16 + TB - 1) / TB, TB>>>(rowp, eixp, yp, rp, b1, hp, N);

    // ---- layer 2 ----
    gemm_dual<64, 64><<<(N + 63) / 64, TB>>>((const float*)hp, w2lp, w2rp,
                                             (float*)yp, (float*)rp, N);
    agg2_k<<<((size_t)N * 16 + TB - 1) / TB, TB>>>(rowp, eixp, yp, rp, b2, Wc, bc, out, N);
}

// round 6
// speedup vs baseline: 1.1264x; 1.1264x over previous
#include <cuda_runtime.h>

#define NNODES 100000
#define NF4    (NNODES * 16)
#define EMAX   1600000

typedef unsigned long long ull;

// ---------------- scratch (device globals; no allocs allowed) ----------------
__device__ float4 g_y[NF4];               // l-path transformed features
__device__ float4 g_r[NF4];               // root-path features
__device__ float4 g_h[NF4];               // hidden activations
__device__ int    g_cnt[NNODES];
__device__ int    g_rowptr[NNODES + 1];
__device__ int    g_cursor[NNODES];
__device__ int    g_eidx[EMAX];

// ---------------- packed f32x2 helpers ----------------
static __device__ __forceinline__ ull pk2(float a, float b) {
    ull r; asm("mov.b64 %0, {%1, %2};" : "=l"(r) : "f"(a), "f"(b)); return r;
}
static __device__ __forceinline__ void ffma2(ull& d, ull a, ull b) {
    asm("fma.rn.f32x2 %0, %1, %2, %0;" : "+l"(d) : "l"(a), "l"(b));
}
static __device__ __forceinline__ float2 upk(ull v) {
    float2 r; asm("mov.b64 {%0, %1}, %2;" : "=f"(r.x), "=f"(r.y) : "l"(v)); return r;
}

// ---------------- CSR build ----------------
__global__ void zero_cnt_k(int* __restrict__ c, int n) {
    int i = blockIdx.x * blockDim.x + threadIdx.x;
    if (i < n) c[i] = 0;
}
__global__ void hist_k(const int* __restrict__ dst, int* __restrict__ cnt, int E) {
    int e = blockIdx.x * blockDim.x + threadIdx.x;
    if (e < E) atomicAdd(&cnt[dst[e]], 1);
}
// single-block exclusive scan of cnt -> rowptr, cursor
__global__ __launch_bounds__(1024) void scan_k(const int* __restrict__ cnt,
                                               int* __restrict__ rowptr,
                                               int* __restrict__ cursor, int N) {
    __shared__ int ssum[1024];
    int t = threadIdx.x;
    int CH = (N + 1023) / 1024;
    int lo = t * CH, hi = min(lo + CH, N);
    int s = 0;
    for (int i = lo; i < hi; i++) s += cnt[i];
    ssum[t] = s;
    __syncthreads();
    for (int off = 1; off < 1024; off <<= 1) {
        int v = 0;
        if (t >= off) v = ssum[t - off];
        __syncthreads();
        if (t >= off) ssum[t] += v;
        __syncthreads();
    }
    int pre = (t == 0) ? 0 : ssum[t - 1];
    for (int i = lo; i < hi; i++) {
        rowptr[i] = pre; cursor[i] = pre;
        pre += cnt[i];
    }
    if (t == 1023) rowptr[N] = ssum[1023];
}
__global__ void fill_k(const int* __restrict__ src, const int* __restrict__ dst,
                       int* __restrict__ cursor, int* __restrict__ eidx, int E) {
    int e = blockIdx.x * blockDim.x + threadIdx.x;
    if (e >= E) return;
    int slot = atomicAdd(&cursor[dst[e]], 1);
    eidx[slot] = src[e];
}

// ---------------- dual GEMM (R2-proven): Yl = X@Wl, Yr = X@Wr ----------
// 64 rows per block, 256 threads: col = tid&63, 16 rows per thread.
template <int K>
__global__ __launch_bounds__(256) void gemm_dual(
    const float* __restrict__ X,
    const float* __restrict__ Wl, const float* __restrict__ Wr,
    float* __restrict__ Yl, float* __restrict__ Yr, int nrows) {
    __shared__ float xsT[K * 68];
    int n0 = blockIdx.x * 64;
    for (int i = threadIdx.x; i < 64 * K; i += 256) {
        int r = i / K, k = i - r * K;
        float v = (n0 + r < nrows) ? X[(size_t)(n0 + r) * K + k] : 0.f;
        xsT[k * 68 + r] = v;
    }
    __syncthreads();

    int col = threadIdx.x & 63;
    int rb  = (threadIdx.x >> 6) * 16;  // 16 rows per thread
    ull accl[8] = {}, accr[8] = {};

    for (int k = 0; k < K; k++) {
        float wl = Wl[k * 64 + col];
        float wr = Wr[k * 64 + col];
        ull wl2 = pk2(wl, wl);
        ull wr2 = pk2(wr, wr);
        const ulonglong2* ap = reinterpret_cast<const ulonglong2*>(&xsT[k * 68 + rb]);
#pragma unroll
        for (int q = 0; q < 4; q++) {
            ulonglong2 a = ap[q];
            ffma2(accl[2 * q],     a.x, wl2);
            ffma2(accr[2 * q],     a.x, wr2);
            ffma2(accl[2 * q + 1], a.y, wl2);
            ffma2(accr[2 * q + 1], a.y, wr2);
        }
    }

#pragma unroll
    for (int p = 0; p < 8; p++) {
        int row = n0 + rb + 2 * p;
        float2 l = upk(accl[p]);
        float2 r = upk(accr[p]);
        if (row < nrows) {
            Yl[(size_t)row * 64 + col] = l.x;
            Yr[(size_t)row * 64 + col] = r.x;
        }
        if (row + 1 < nrows) {
            Yl[(size_t)(row + 1) * 64 + col] = l.y;
            Yr[(size_t)(row + 1) * 64 + col] = r.y;
        }
    }
}

// ---------------- layer-1 aggregate + finalize: h = relu(mean + b + r) ----------------
__global__ void agg1_k(const int* __restrict__ rowptr, const int* __restrict__ eidx,
                       const float4* __restrict__ y, const float4* __restrict__ r,
                       const float* __restrict__ b, float4* __restrict__ h, int N) {
    int t = blockIdx.x * blockDim.x + threadIdx.x;
    int node = t >> 4, c = t & 15;
    if (node >= N) return;
    int beg = rowptr[node], end = rowptr[node + 1];
    float4 acc = make_float4(0.f, 0.f, 0.f, 0.f);
    float4 acc2 = make_float4(0.f, 0.f, 0.f, 0.f);
    int j = beg;
    for (; j + 2 <= end; j += 2) {
        int s0 = __ldg(&eidx[j]), s1 = __ldg(&eidx[j + 1]);
        float4 v0 = y[(size_t)s0 * 16 + c];
        float4 v1 = y[(size_t)s1 * 16 + c];
        acc.x += v0.x; acc.y += v0.y; acc.z += v0.z; acc.w += v0.w;
        acc2.x += v1.x; acc2.y += v1.y; acc2.z += v1.z; acc2.w += v1.w;
    }
    if (j < end) {
        int s0 = __ldg(&eidx[j]);
        float4 v0 = y[(size_t)s0 * 16 + c];
        acc.x += v0.x; acc.y += v0.y; acc.z += v0.z; acc.w += v0.w;
    }
    acc.x += acc2.x; acc.y += acc2.y; acc.z += acc2.z; acc.w += acc2.w;
    float inv = 1.f / fmaxf((float)(end - beg), 1.f);
    float4 rr = r[(size_t)node * 16 + c];
    float4 bb = reinterpret_cast<const float4*>(b)[c];
    float4 o;
    o.x = fmaxf(fmaf(acc.x, inv, bb.x + rr.x), 0.f);
    o.y = fmaxf(fmaf(acc.y, inv, bb.y + rr.y), 0.f);
    o.z = fmaxf(fmaf(acc.z, inv, bb.z + rr.z), 0.f);
    o.w = fmaxf(fmaf(acc.w, inv, bb.w + rr.w), 0.f);
    h[(size_t)node * 16 + c] = o;
}

// ------- layer-2 aggregate + finalize + classifier: out = relu(mean+b+r) @ Wc + bc ----
__global__ void agg2_k(const int* __restrict__ rowptr, const int* __restrict__ eidx,
                       const float4* __restrict__ y, const float4* __restrict__ r,
                       const float* __restrict__ b, const float* __restrict__ Wc,
                       const float* __restrict__ bc, float* __restrict__ out, int N) {
    int t = blockIdx.x * blockDim.x + threadIdx.x;
    int node = t >> 4, c = t & 15;
    if (node >= N) return;
    int beg = rowptr[node], end = rowptr[node + 1];
    float4 acc = make_float4(0.f, 0.f, 0.f, 0.f);
    float4 acc2 = make_float4(0.f, 0.f, 0.f, 0.f);
    int j = beg;
    for (; j + 2 <= end; j += 2) {
        int s0 = __ldg(&eidx[j]), s1 = __ldg(&eidx[j + 1]);
        float4 v0 = y[(size_t)s0 * 16 + c];
        float4 v1 = y[(size_t)s1 * 16 + c];
        acc.x += v0.x; acc.y += v0.y; acc.z += v0.z; acc.w += v0.w;
        acc2.x += v1.x; acc2.y += v1.y; acc2.z += v1.z; acc2.w += v1.w;
    }
    if (j < end) {
        int s0 = __ldg(&eidx[j]);
        float4 v0 = y[(size_t)s0 * 16 + c];
        acc.x += v0.x; acc.y += v0.y; acc.z += v0.z; acc.w += v0.w;
    }
    acc.x += acc2.x; acc.y += acc2.y; acc.z += acc2.z; acc.w += acc2.w;
    float inv = 1.f / fmaxf((float)(end - beg), 1.f);
    float4 rr = r[(size_t)node * 16 + c];
    float4 bb = reinterpret_cast<const float4*>(b)[c];
    float4 hv;
    hv.x = fmaxf(fmaf(acc.x, inv, bb.x + rr.x), 0.f);
    hv.y = fmaxf(fmaf(acc.y, inv, bb.y + rr.y), 0.f);
    hv.z = fmaxf(fmaf(acc.z, inv, bb.z + rr.z), 0.f);
    hv.w = fmaxf(fmaf(acc.w, inv, bb.w + rr.w), 0.f);
    // classifier partials: rows 4c..4c+3 of Wc[64,2]
    float4 wc0 = reinterpret_cast<const float4*>(Wc)[2 * c];
    float4 wc1 = reinterpret_cast<const float4*>(Wc)[2 * c + 1];
    float a0 = hv.x * wc0.x + hv.y * wc0.z + hv.z * wc1.x + hv.w * wc1.z;
    float a1 = hv.x * wc0.y + hv.y * wc0.w + hv.z * wc1.y + hv.w * wc1.w;
#pragma unroll
    for (int o = 8; o; o >>= 1) {
        a0 += __shfl_xor_sync(0xffffffffu, a0, o);
        a1 += __shfl_xor_sync(0xffffffffu, a1, o);
    }
    if (c == 0) {
        out[node * 2]     = a0 + bc[0];
        out[node * 2 + 1] = a1 + bc[1];
    }
}

extern "C" void kernel_launch(void* const* d_in, const int* in_sizes, int n_in,
                              void* d_out, int out_size) {
    const float* x   = (const float*)d_in[0];
    const int*   ei  = (const int*)d_in[1];
    const float* W1l = (const float*)d_in[2];
    const float* b1  = (const float*)d_in[3];
    const float* W1r = (const float*)d_in[4];
    const float* W2l = (const float*)d_in[5];
    const float* b2  = (const float*)d_in[6];
    const float* W2r = (const float*)d_in[7];
    const float* Wc  = (const float*)d_in[8];
    const float* bc  = (const float*)d_in[9];
    float* out = (float*)d_out;

    const int N = in_sizes[0] / 165;
    const int E = in_sizes[1] / 2;
    const int* src = ei;
    const int* dst = ei + E;

    float4 *yp, *rp, *hp;
    int *cntp, *rowp, *curp, *eixp;
    cudaGetSymbolAddress((void**)&yp,   g_y);
    cudaGetSymbolAddress((void**)&rp,   g_r);
    cudaGetSymbolAddress((void**)&hp,   g_h);
    cudaGetSymbolAddress((void**)&cntp, g_cnt);
    cudaGetSymbolAddress((void**)&rowp, g_rowptr);
    cudaGetSymbolAddress((void**)&curp, g_cursor);
    cudaGetSymbolAddress((void**)&eixp, g_eidx);

    const int TB = 256;

    // CSR build (shared by both layers)
    zero_cnt_k<<<(N + TB - 1) / TB, TB>>>(cntp, N);
    hist_k<<<(E + TB - 1) / TB, TB>>>(dst, cntp, E);
    scan_k<<<1, 1024>>>(cntp, rowp, curp, N);
    fill_k<<<(E + TB - 1) / TB, TB>>>(src, dst, curp, eixp, E);

    // ---- layer 1 ----
    gemm_dual<165><<<(N + 63) / 64, TB>>>(x, W1l, W1r, (float*)yp, (float*)rp, N);
    agg1_k<<<((size_t)N * 16 + TB - 1) / TB, TB>>>(rowp, eixp, yp, rp, b1, hp, N);

    // ---- layer 2 ----
    gemm_dual<64><<<(N + 63) / 64, TB>>>((const float*)hp, W2l, W2r,
                                         (float*)yp, (float*)rp, N);
    agg2_k<<<((size_t)N * 16 + TB - 1) / TB, TB>>>(rowp, eixp, yp, rp, b2, Wc, bc, out, N);
}

// round 8
// speedup vs baseline: 1.1746x; 1.0428x over previous
#include <cuda_runtime.h>
#include <cstdint>

#define NNODES 100000
#define NF4    (NNODES * 16)

// ---------------- scratch (device globals; no allocs allowed) ----------------
__device__ float4 g_y[NF4];     // l-path transformed features
__device__ float4 g_r[NF4];     // root-path features
__device__ float4 g_agg[NF4];   // scatter accumulator
__device__ float4 g_h[NF4];     // hidden activations
__device__ float  g_deg[NNODES];

// ---------------- helpers ----------------
static __device__ __forceinline__ uint32_t tf32_rna(float v) {
    uint32_t o;
    asm("cvt.rna.tf32.f32 %0, %1;" : "=r"(o) : "f"(v));
    return o;
}
static __device__ __forceinline__ void mma_tf32(float& d0, float& d1, float& d2, float& d3,
                                                uint32_t a0, uint32_t a1, uint32_t a2, uint32_t a3,
                                                uint32_t b0, uint32_t b1) {
    asm volatile("mma.sync.aligned.m16n8k8.row.col.f32.tf32.tf32.f32 "
                 "{%0,%1,%2,%3}, {%4,%5,%6,%7}, {%8,%9}, {%0,%1,%2,%3};"
                 : "+f"(d0), "+f"(d1), "+f"(d2), "+f"(d3)
                 : "r"(a0), "r"(a1), "r"(a2), "r"(a3), "r"(b0), "r"(b1));
}

// ---------------- utility kernels ----------------
__global__ void zero_k(float4* __restrict__ p, int n) {
    int i = blockIdx.x * blockDim.x + threadIdx.x;
    if (i < n) p[i] = make_float4(0.f, 0.f, 0.f, 0.f);
}
__global__ void deg_k(const int* __restrict__ dst, float* __restrict__ deg, int E) {
    int e = blockIdx.x * blockDim.x + threadIdx.x;
    if (e < E) atomicAdd(&deg[dst[e]], 1.0f);
}

// ================= tf32 mma.sync dual GEMM =================
// Per CTA: 128 rows, Yl = X@Wl and Yr = X@Wr (64 cols each).
// smem holds tf32 operands in FRAGMENT-MAJOR layout (mma register order):
//   afrag[kt][mtile(8)][lane(32)][reg(4)]  -> LDS.128 per thread
//   bfrag[kt][ntile(8)][lane(32)][reg(2)]  -> LDS.64  per thread
// Warps 0-3: path L (rows 32w..32w+31, all 64 cols); warps 4-7: path R.
template <int K, int K8, bool ZERO>
__global__ __launch_bounds__(256, 1) void gemm_mma(
    const float* __restrict__ X,
    const float* __restrict__ Wl, const float* __restrict__ Wr,
    float* __restrict__ Yl, float* __restrict__ Yr, int nrows) {
    extern __shared__ uint32_t sm[];
    const int A_OFF  = 0;                 // K8*1024 words
    const int BL_OFF = K8 * 1024;         // K8*512 words
    const int BR_OFF = K8 * 1536;
    const int TOTAL  = K8 * 2048;

    int tid = threadIdx.x;
    int n0 = blockIdx.x * 128;

    if (ZERO) {
        for (int i = tid; i < TOTAL / 4; i += 256)
            reinterpret_cast<uint4*>(sm)[i] = make_uint4(0u, 0u, 0u, 0u);
        __syncthreads();
    }

    // ---- fill A fragments (tf32-rounded) ----
    for (int idx = tid; idx < 128 * K; idx += 256) {
        int row = idx / K, k = idx - row * K;
        float v = (n0 + row < nrows) ? X[(size_t)(n0 + row) * K + k] : 0.f;
        int m = row >> 4, r = row & 15, kt = k >> 3, c = k & 7;
        int lane = ((r & 7) << 2) | (c & 3);
        int reg  = (r >> 3) | ((c >> 2) << 1);
        sm[A_OFF + (((kt * 8 + m) * 32 + lane) << 2) + reg] = tf32_rna(v);
    }
    // ---- fill B fragments for both paths ----
    for (int idx = tid; idx < K * 64; idx += 256) {
        int k = idx >> 6, n = idx & 63;
        int kt = k >> 3, c = k & 7, nt = n >> 3, nn = n & 7;
        int lane = (nn << 2) | (c & 3);
        int reg  = c >> 2;
        int off = (((kt * 8 + nt) * 32 + lane) << 1) + reg;
        sm[BL_OFF + off] = tf32_rna(Wl[k * 64 + n]);
        sm[BR_OFF + off] = tf32_rna(Wr[k * 64 + n]);
    }
    __syncthreads();

    int wid = tid >> 5, lane = tid & 31;
    int path = wid >> 2;          // 0 = L, 1 = R
    int mw   = wid & 3;           // rows 32*mw .. 32*mw+31 (m-tiles 2mw, 2mw+1)
    const int B_OFF = path ? BR_OFF : BL_OFF;

    float acc[2][8][4];
#pragma unroll
    for (int mi = 0; mi < 2; mi++)
#pragma unroll
        for (int nt = 0; nt < 8; nt++)
#pragma unroll
            for (int q = 0; q < 4; q++) acc[mi][nt][q] = 0.f;

    for (int kt = 0; kt < K8; kt++) {
        uint4 a0 = reinterpret_cast<const uint4*>(sm + A_OFF)[(kt * 8 + 2 * mw) * 32 + lane];
        uint4 a1 = reinterpret_cast<const uint4*>(sm + A_OFF)[(kt * 8 + 2 * mw + 1) * 32 + lane];
        uint2 b[8];
#pragma unroll
        for (int nt = 0; nt < 8; nt++)
            b[nt] = reinterpret_cast<const uint2*>(sm + B_OFF)[(kt * 8 + nt) * 32 + lane];
#pragma unroll
        for (int nt = 0; nt < 8; nt++) {
            mma_tf32(acc[0][nt][0], acc[0][nt][1], acc[0][nt][2], acc[0][nt][3],
                     a0.x, a0.y, a0.z, a0.w, b[nt].x, b[nt].y);
            mma_tf32(acc[1][nt][0], acc[1][nt][1], acc[1][nt][2], acc[1][nt][3],
                     a1.x, a1.y, a1.z, a1.w, b[nt].x, b[nt].y);
        }
    }

    // ---- epilogue: direct STG (c0,c1 -> row, c2,c3 -> row+8) ----
    float* Y = path ? Yr : Yl;
#pragma unroll
    for (int mi = 0; mi < 2; mi++) {
        int rbase = n0 + mw * 32 + mi * 16 + (lane >> 2);
        int col = (lane & 3) * 2;
#pragma unroll
        for (int nt = 0; nt < 8; nt++) {
            int c = nt * 8 + col;
            if (rbase < nrows)
                *reinterpret_cast<float2*>(&Y[(size_t)rbase * 64 + c]) =
                    make_float2(acc[mi][nt][0], acc[mi][nt][1]);
            if (rbase + 8 < nrows)
                *reinterpret_cast<float2*>(&Y[(size_t)(rbase + 8) * 64 + c]) =
                    make_float2(acc[mi][nt][2], acc[mi][nt][3]);
        }
    }
}

// ---------------- edge scatter: agg[dst] += y[src] (16 float4 per edge) ----------------
__global__ void scat_k(const int* __restrict__ src, const int* __restrict__ dst,
                       const float4* __restrict__ y, float4* __restrict__ agg, int E) {
    int idx = blockIdx.x * blockDim.x + threadIdx.x;
    if (idx >= E * 16) return;
    int e = idx >> 4, c = idx & 15;
    int s = src[e], d = dst[e];
    float4 v = y[(size_t)s * 16 + c];
    atomicAdd(&agg[(size_t)d * 16 + c], v);
}

// ---------------- finalize layer: h = relu(agg/max(deg,1) + b + r) ----------------
__global__ void fin_k(const float4* __restrict__ agg, const float4* __restrict__ r,
                      const float* __restrict__ deg, const float* __restrict__ b,
                      float4* __restrict__ h, int n4) {
    int i = blockIdx.x * blockDim.x + threadIdx.x;
    if (i >= n4) return;
    int node = i >> 4, c = i & 15;
    float inv = 1.f / fmaxf(deg[node], 1.f);
    float4 a = agg[i], rr = r[i];
    float4 bb = reinterpret_cast<const float4*>(b)[c];
    float4 o;
    o.x = fmaxf(fmaf(a.x, inv, bb.x + rr.x), 0.f);
    o.y = fmaxf(fmaf(a.y, inv, bb.y + rr.y), 0.f);
    o.z = fmaxf(fmaf(a.z, inv, bb.z + rr.z), 0.f);
    o.w = fmaxf(fmaf(a.w, inv, bb.w + rr.w), 0.f);
    h[i] = o;
}

// ------- fused finalize layer2 + classifier ----------------
__global__ void fin2_k(const float* __restrict__ agg, const float* __restrict__ r,
                       const float* __restrict__ deg, const float* __restrict__ b,
                       const float* __restrict__ Wc, const float* __restrict__ bc,
                       float* __restrict__ out, int n) {
    int t = blockIdx.x * blockDim.x + threadIdx.x;
    int node = t >> 5, lane = t & 31;
    if (node >= n) return;
    float inv = 1.f / fmaxf(deg[node], 1.f);
    float a0 = 0.f, a1 = 0.f;
#pragma unroll
    for (int q = 0; q < 2; q++) {
        int j = lane + q * 32;
        float hv = fmaxf(fmaf(agg[(size_t)node * 64 + j], inv,
                              b[j] + r[(size_t)node * 64 + j]), 0.f);
        a0 = fmaf(hv, Wc[2 * j], a0);
        a1 = fmaf(hv, Wc[2 * j + 1], a1);
    }
#pragma unroll
    for (int o = 16; o; o >>= 1) {
        a0 += __shfl_xor_sync(0xffffffffu, a0, o);
        a1 += __shfl_xor_sync(0xffffffffu, a1, o);
    }
    if (lane == 0) {
        out[node * 2]     = a0 + bc[0];
        out[node * 2 + 1] = a1 + bc[1];
    }
}

extern "C" void kernel_launch(void* const* d_in, const int* in_sizes, int n_in,
                              void* d_out, int out_size) {
    const float* x   = (const float*)d_in[0];
    const int*   ei  = (const int*)d_in[1];
    const float* W1l = (const float*)d_in[2];
    const float* b1  = (const float*)d_in[3];
    const float* W1r = (const float*)d_in[4];
    const float* W2l = (const float*)d_in[5];
    const float* b2  = (const float*)d_in[6];
    const float* W2r = (const float*)d_in[7];
    const float* Wc  = (const float*)d_in[8];
    const float* bc  = (const float*)d_in[9];
    float* out = (float*)d_out;

    const int N = in_sizes[0] / 165;
    const int E = in_sizes[1] / 2;
    const int* src = ei;
    const int* dst = ei + E;

    float4 *yp, *rp, *aggp, *hp;
    float* degp;
    cudaGetSymbolAddress((void**)&yp,   g_y);
    cudaGetSymbolAddress((void**)&rp,   g_r);
    cudaGetSymbolAddress((void**)&aggp, g_agg);
    cudaGetSymbolAddress((void**)&hp,   g_h);
    cudaGetSymbolAddress((void**)&degp, g_deg);

    const int n4 = N * 16;
    const int TB = 256;
    const int SM1 = 21 * 2048 * 4;   // 172032 B (K=165 -> K8=21)
    const int SM2 = 8 * 2048 * 4;    //  65536 B (K=64  -> K8=8)

    static bool attr_done = false;
    if (!attr_done) {
        cudaFuncSetAttribute(gemm_mma<165, 21, true>,
                             cudaFuncAttributeMaxDynamicSharedMemorySize, SM1);
        cudaFuncSetAttribute(gemm_mma<64, 8, false>,
                             cudaFuncAttributeMaxDynamicSharedMemorySize, SM2);
        attr_done = true;
    }

    // degree (shared by both layers)
    zero_k<<<(N / 4 + TB - 1) / TB, TB>>>((float4*)degp, N / 4);
    deg_k<<<(E + TB - 1) / TB, TB>>>(dst, degp, E);

    // ---- layer 1 ----
    zero_k<<<(n4 + TB - 1) / TB, TB>>>(aggp, n4);
    gemm_mma<165, 21, true><<<(N + 127) / 128, TB, SM1>>>(x, W1l, W1r,
                                                          (float*)yp, (float*)rp, N);
    scat_k<<<((size_t)E * 16 + TB - 1) / TB, TB>>>(src, dst, yp, aggp, E);
    fin_k<<<(n4 + TB - 1) / TB, TB>>>(aggp, rp, degp, b1, hp, n4);

    // ---- layer 2 ----
    zero_k<<<(n4 + TB - 1) / TB, TB>>>(aggp, n4);
    gemm_mma<64, 8, false><<<(N + 127) / 128, TB, SM2>>>((const float*)hp, W2l, W2r,
                                                         (float*)yp, (float*)rp, N);
    scat_k<<<((size_t)E * 16 + TB - 1) / TB, TB>>>(src, dst, yp, aggp, E);

    // ---- finalize + classifier ----
    fin2_k<<<((size_t)N * 32 + TB - 1) / TB, TB>>>((const float*)aggp, (const float*)rp,
                                                   degp, b2, Wc, bc, out, N);
}

// round 10
// speedup vs baseline: 1.4805x; 1.2604x over previous
#include <cuda_runtime.h>
#include <cstdint>

#define NNODES 100000
#define NF4    (NNODES * 16)

// ---------------- scratch (device globals; no allocs allowed) ----------------
__device__ float4 g_y[NF4];
__device__ float4 g_r[NF4];
__device__ float4 g_agg[NF4];
__device__ float4 g_h[NF4];
__device__ float  g_deg[NNODES];
// tf32 fragment-major weights: [kt][nt][lane] uint2 ; layer1: 21*8*32, layer2: 8*8*32
__device__ uint2  g_bl1[5376], g_br1[5376];
__device__ uint2  g_bl2[2048], g_br2[2048];

// ---------------- helpers ----------------
static __device__ __forceinline__ uint32_t tf32_rna(float v) {
    uint32_t o;
    asm("cvt.rna.tf32.f32 %0, %1;" : "=r"(o) : "f"(v));
    return o;
}
static __device__ __forceinline__ void mma_tf32(float& d0, float& d1, float& d2, float& d3,
                                                uint32_t a0, uint32_t a1, uint32_t a2, uint32_t a3,
                                                uint32_t b0, uint32_t b1) {
    asm volatile("mma.sync.aligned.m16n8k8.row.col.f32.tf32.tf32.f32 "
                 "{%0,%1,%2,%3}, {%4,%5,%6,%7}, {%8,%9}, {%0,%1,%2,%3};"
                 : "+f"(d0), "+f"(d1), "+f"(d2), "+f"(d3)
                 : "r"(a0), "r"(a1), "r"(a2), "r"(a3), "r"(b0), "r"(b1));
}

// ---------------- utility kernels ----------------
__global__ void zero_k(float4* __restrict__ p, int n) {
    int i = blockIdx.x * blockDim.x + threadIdx.x;
    if (i < n) p[i] = make_float4(0.f, 0.f, 0.f, 0.f);
}
__global__ void deg_k(const int* __restrict__ dst, float* __restrict__ deg, int E) {
    int e = blockIdx.x * blockDim.x + threadIdx.x;
    if (e < E) atomicAdd(&deg[dst[e]], 1.0f);
}

// ---------------- weight fragment pack: W[K,64] -> frag[kt*8+nt][lane] (uint2) ------
__global__ void pack_b(const float* __restrict__ W, uint2* __restrict__ F, int K, int K8) {
    int i = blockIdx.x * blockDim.x + threadIdx.x;
    if (i >= K8 * 8 * 32) return;
    int lane = i & 31, nt = (i >> 5) & 7, kt = i >> 8;
    int k = kt * 8 + (lane & 3);
    int n = nt * 8 + (lane >> 2);
    uint2 v;
    v.x = (k     < K) ? tf32_rna(W[k * 64 + n])       : 0u;
    v.y = (k + 4 < K) ? tf32_rna(W[(k + 4) * 64 + n]) : 0u;
    F[i] = v;
}

// ================= tf32 mma.sync dual GEMM =================
// Per CTA: 128 rows. smem = X rows flat row-major (fp32). B fragments from gmem (L1-hot).
// Warps 0-3: L path (rows 32w..32w+31, 64 cols); warps 4-7: R path.
template <int K, int K8>
__global__ __launch_bounds__(256, 1) void gemm_mma(
    const float* __restrict__ X,
    const uint2* __restrict__ BL, const uint2* __restrict__ BR,
    float* __restrict__ Yl, float* __restrict__ Yr, int nrows) {
    extern __shared__ float smA[];           // 128*K floats, flat
    int tid = threadIdx.x;
    int n0 = blockIdx.x * 128;

    // ---- fill: flat float4 copy ----
    int rows = min(128, nrows - n0);
    int cnt = rows * K;
    const float4* srcv = reinterpret_cast<const float4*>(X + (size_t)n0 * K);
    int nf4 = cnt >> 2;
    for (int i = tid; i < (128 * K) >> 2; i += 256) {
        float4 v = (i < nf4) ? srcv[i] : make_float4(0.f, 0.f, 0.f, 0.f);
        reinterpret_cast<float4*>(smA)[i] = v;
    }
    if (tid < (cnt & 3)) smA[(nf4 << 2) + tid] = X[(size_t)n0 * K + (nf4 << 2) + tid];
    __syncthreads();

    int wid = tid >> 5, lane = tid & 31;
    int path = wid >> 2;                     // 0 = L, 1 = R
    int mw = wid & 3;                        // row block 32*mw
    const uint2* B = path ? BR : BL;

    int r0 = mw * 32 + (lane >> 2);
    int kc = lane & 3;
    const float* A0 = smA + r0 * K;          // rows r0, r0+8, r0+16, r0+24

    float acc[2][8][4];
#pragma unroll
    for (int mi = 0; mi < 2; mi++)
#pragma unroll
        for (int nt = 0; nt < 8; nt++)
#pragma unroll
            for (int q = 0; q < 4; q++) acc[mi][nt][q] = 0.f;

    // full k-tiles (all indices < K guaranteed: (K8-2)*8 + 3 + 4 < K)
    int kt = 0;
    for (; kt < K8 - 1; kt++) {
        int kb = kt * 8 + kc;
        uint32_t a[8];
        a[0] = tf32_rna(A0[kb]);
        a[1] = tf32_rna(A0[8 * K + kb]);
        a[2] = tf32_rna(A0[kb + 4]);
        a[3] = tf32_rna(A0[8 * K + kb + 4]);
        a[4] = tf32_rna(A0[16 * K + kb]);
        a[5] = tf32_rna(A0[24 * K + kb]);
        a[6] = tf32_rna(A0[16 * K + kb + 4]);
        a[7] = tf32_rna(A0[24 * K + kb + 4]);
        uint2 b[8];
#pragma unroll
        for (int nt = 0; nt < 8; nt++) b[nt] = __ldg(&B[(kt * 8 + nt) * 32 + lane]);
#pragma unroll
        for (int nt = 0; nt < 8; nt++) {
            mma_tf32(acc[0][nt][0], acc[0][nt][1], acc[0][nt][2], acc[0][nt][3],
                     a[0], a[1], a[2], a[3], b[nt].x, b[nt].y);
            mma_tf32(acc[1][nt][0], acc[1][nt][1], acc[1][nt][2], acc[1][nt][3],
                     a[4], a[5], a[6], a[7], b[nt].x, b[nt].y);
        }
    }
    // peeled last k-tile: predicate A column indices against K (B is zero-padded
    // there, so the value is irrelevant; only the address must stay in bounds).
    {
        int kb = kt * 8 + kc;
        bool in0 = (kb < K), in1 = (kb + 4 < K);
        uint32_t a[8];
        a[0] = in0 ? tf32_rna(A0[kb])              : 0u;
        a[1] = in0 ? tf32_rna(A0[8 * K + kb])      : 0u;
        a[2] = in1 ? tf32_rna(A0[kb + 4])          : 0u;
        a[3] = in1 ? tf32_rna(A0[8 * K + kb + 4])  : 0u;
        a[4] = in0 ? tf32_rna(A0[16 * K + kb])     : 0u;
        a[5] = in0 ? tf32_rna(A0[24 * K + kb])     : 0u;
        a[6] = in1 ? tf32_rna(A0[16 * K + kb + 4]) : 0u;
        a[7] = in1 ? tf32_rna(A0[24 * K + kb + 4]) : 0u;
        uint2 b[8];
#pragma unroll
        for (int nt = 0; nt < 8; nt++) b[nt] = __ldg(&B[(kt * 8 + nt) * 32 + lane]);
#pragma unroll
        for (int nt = 0; nt < 8; nt++) {
            mma_tf32(acc[0][nt][0], acc[0][nt][1], acc[0][nt][2], acc[0][nt][3],
                     a[0], a[1], a[2], a[3], b[nt].x, b[nt].y);
            mma_tf32(acc[1][nt][0], acc[1][nt][1], acc[1][nt][2], acc[1][nt][3],
                     a[4], a[5], a[6], a[7], b[nt].x, b[nt].y);
        }
    }

    // ---- epilogue: direct STG (verified R8 mapping) ----
    float* Y = path ? Yr : Yl;
#pragma unroll
    for (int mi = 0; mi < 2; mi++) {
        int rbase = n0 + mw * 32 + mi * 16 + (lane >> 2);
        int col = (lane & 3) * 2;
#pragma unroll
        for (int nt = 0; nt < 8; nt++) {
            int c = nt * 8 + col;
            if (rbase < nrows)
                *reinterpret_cast<float2*>(&Y[(size_t)rbase * 64 + c]) =
                    make_float2(acc[mi][nt][0], acc[mi][nt][1]);
            if (rbase + 8 < nrows)
                *reinterpret_cast<float2*>(&Y[(size_t)(rbase + 8) * 64 + c]) =
                    make_float2(acc[mi][nt][2], acc[mi][nt][3]);
        }
    }
}

// ---------------- edge scatter: agg[dst] += y[src] ----------------
__global__ void scat_k(const int* __restrict__ src, const int* __restrict__ dst,
                       const float4* __restrict__ y, float4* __restrict__ agg, int E) {
    int idx = blockIdx.x * blockDim.x + threadIdx.x;
    if (idx >= E * 16) return;
    int e = idx >> 4, c = idx & 15;
    int s = src[e], d = dst[e];
    float4 v = y[(size_t)s * 16 + c];
    atomicAdd(&agg[(size_t)d * 16 + c], v);
}

// ---------------- finalize layer: h = relu(agg/max(deg,1) + b + r) ----------------
__global__ void fin_k(const float4* __restrict__ agg, const float4* __restrict__ r,
                      const float* __restrict__ deg, const float* __restrict__ b,
                      float4* __restrict__ h, int n4) {
    int i = blockIdx.x * blockDim.x + threadIdx.x;
    if (i >= n4) return;
    int node = i >> 4, c = i & 15;
    float inv = 1.f / fmaxf(deg[node], 1.f);
    float4 a = agg[i], rr = r[i];
    float4 bb = reinterpret_cast<const float4*>(b)[c];
    float4 o;
    o.x = fmaxf(fmaf(a.x, inv, bb.x + rr.x), 0.f);
    o.y = fmaxf(fmaf(a.y, inv, bb.y + rr.y), 0.f);
    o.z = fmaxf(fmaf(a.z, inv, bb.z + rr.z), 0.f);
    o.w = fmaxf(fmaf(a.w, inv, bb.w + rr.w), 0.f);
    h[i] = o;
}

// ------- fused finalize layer2 + classifier ----------------
__global__ void fin2_k(const float* __restrict__ agg, const float* __restrict__ r,
                       const float* __restrict__ deg, const float* __restrict__ b,
                       const float* __restrict__ Wc, const float* __restrict__ bc,
                       float* __restrict__ out, int n) {
    int t = blockIdx.x * blockDim.x + threadIdx.x;
    int node = t >> 5, lane = t & 31;
    if (node >= n) return;
    float inv = 1.f / fmaxf(deg[node], 1.f);
    float a0 = 0.f, a1 = 0.f;
#pragma unroll
    for (int q = 0; q < 2; q++) {
        int j = lane + q * 32;
        float hv = fmaxf(fmaf(agg[(size_t)node * 64 + j], inv,
                              b[j] + r[(size_t)node * 64 + j]), 0.f);
        a0 = fmaf(hv, Wc[2 * j], a0);
        a1 = fmaf(hv, Wc[2 * j + 1], a1);
    }
#pragma unroll
    for (int o = 16; o; o >>= 1) {
        a0 += __shfl_xor_sync(0xffffffffu, a0, o);
        a1 += __shfl_xor_sync(0xffffffffu, a1, o);
    }
    if (lane == 0) {
        out[node * 2]     = a0 + bc[0];
        out[node * 2 + 1] = a1 + bc[1];
    }
}

extern "C" void kernel_launch(void* const* d_in, const int* in_sizes, int n_in,
                              void* d_out, int out_size) {
    const float* x   = (const float*)d_in[0];
    const int*   ei  = (const int*)d_in[1];
    const float* W1l = (const float*)d_in[2];
    const float* b1  = (const float*)d_in[3];
    const float* W1r = (const float*)d_in[4];
    const float* W2l = (const float*)d_in[5];
    const float* b2  = (const float*)d_in[6];
    const float* W2r = (const float*)d_in[7];
    const float* Wc  = (const float*)d_in[8];
    const float* bc  = (const float*)d_in[9];
    float* out = (float*)d_out;

    const int N = in_sizes[0] / 165;
    const int E = in_sizes[1] / 2;
    const int* src = ei;
    const int* dst = ei + E;

    float4 *yp, *rp, *aggp, *hp;
    float* degp;
    uint2 *bl1, *br1, *bl2, *br2;
    cudaGetSymbolAddress((void**)&yp,   g_y);
    cudaGetSymbolAddress((void**)&rp,   g_r);
    cudaGetSymbolAddress((void**)&aggp, g_agg);
    cudaGetSymbolAddress((void**)&hp,   g_h);
    cudaGetSymbolAddress((void**)&degp, g_deg);
    cudaGetSymbolAddress((void**)&bl1,  g_bl1);
    cudaGetSymbolAddress((void**)&br1,  g_br1);
    cudaGetSymbolAddress((void**)&bl2,  g_bl2);
    cudaGetSymbolAddress((void**)&br2,  g_br2);

    const int n4 = N * 16;
    const int TB = 256;
    const int SM1 = 128 * 165 * 4;   // 84480 B
    const int SM2 = 128 * 64 * 4;    // 32768 B

    static bool attr_done = false;
    if (!attr_done) {
        cudaFuncSetAttribute(gemm_mma<165, 21>,
                             cudaFuncAttributeMaxDynamicSharedMemorySize, SM1);
        cudaFuncSetAttribute(gemm_mma<64, 8>,
                             cudaFuncAttributeMaxDynamicSharedMemorySize, SM2);
        attr_done = true;
    }

    // weight fragment packing (cheap)
    pack_b<<<(5376 + TB - 1) / TB, TB>>>(W1l, bl1, 165, 21);
    pack_b<<<(5376 + TB - 1) / TB, TB>>>(W1r, br1, 165, 21);
    pack_b<<<(2048 + TB - 1) / TB, TB>>>(W2l, bl2, 64, 8);
    pack_b<<<(2048 + TB - 1) / TB, TB>>>(W2r, br2, 64, 8);

    // degree (shared by both layers)
    zero_k<<<(N / 4 + TB - 1) / TB, TB>>>((float4*)degp, N / 4);
    deg_k<<<(E + TB - 1) / TB, TB>>>(dst, degp, E);

    // ---- layer 1 ----
    zero_k<<<(n4 + TB - 1) / TB, TB>>>(aggp, n4);
    gemm_mma<165, 21><<<(N + 127) / 128, TB, SM1>>>(x, bl1, br1,
                                                    (float*)yp, (float*)rp, N);
    scat_k<<<((size_t)E * 16 + TB - 1) / TB, TB>>>(src, dst, yp, aggp, E);
    fin_k<<<(n4 + TB - 1) / TB, TB>>>(aggp, rp, degp, b1, hp, n4);

    // ---- layer 2 ----
    zero_k<<<(n4 + TB - 1) / TB, TB>>>(aggp, n4);
    gemm_mma<64, 8><<<(N + 127) / 128, TB, SM2>>>((const float*)hp, bl2, br2,
                                                  (float*)yp, (float*)rp, N);
    scat_k<<<((size_t)E * 16 + TB - 1) / TB, TB>>>(src, dst, yp, aggp, E);

    // ---- finalize + classifier ----
    fin2_k<<<((size_t)N * 32 + TB - 1) / TB, TB>>>((const float*)aggp, (const float*)rp,
                                                   degp, b2, Wc, bc, out, N);
}